// round 6
// baseline (speedup 1.0000x reference)
#include <cuda_runtime.h>
#include <cuda_bf16.h>

#define BB 8
#define PP 196
#define ROWS (BB*PP)   // 1568
#define IT 7
#define NIT 28         // i-tiles per batch
#define JT 14          // j-tile size
#define NT 7           // j-tiles per half (7*14 = 98)
#define K2P 20         // padded pitch for k2 rows (16 used)

// Scratch (allocation-free rule: __device__ globals)
__device__ __align__(16) float g_G[ROWS * 256];       // G[b,j][h*16+d]
__device__ __align__(16) float g_feat[ROWS * 32];
__device__ __align__(16) float g_part[2 * ROWS * 16]; // j-half partial sums
__device__ float g_Sbias[BB * 16];

// feat_G dynamic-smem layout (floats):
#define FG_W1   0                    // 124*32 = 3968
#define FG_W2   (FG_W1 + 3968)       // 512
#define FG_W3   (FG_W2 + 512)        // 512
#define FG_B1   (FG_W3 + 512)        // 32
#define FG_B2   (FG_B1 + 32)         // 16
#define FG_B3   (FG_B2 + 16)         // 32
#define FG_KW   (FG_B3 + 32)         // 32*264 = 8448
#define FG_X    (FG_KW + 8448)       // 8*128 = 1024 (pitch 128, 16B aligned)
#define FG_H1   (FG_X + 1024)        // 8*32 = 256
#define FG_H2   (FG_H1 + 256)        // 8*16 = 128
#define FG_F    (FG_H2 + 128)        // 8*32 = 256 (pitch 32, 16B aligned)
#define FG_TOT  (FG_F + 256)         // 15184 floats = 60736 B

// ---------------------------------------------------------------------------
// Kernel A (fused): decode MLP -> feat, then G = feat @ reordered kW3.
// 196 blocks x 256 threads; warp-per-row decode (8 rows), thread-per-column G.
// ---------------------------------------------------------------------------
__global__ __launch_bounds__(256) void feat_G_kernel(
    const float* __restrict__ feature, const float* __restrict__ pe,
    const float* __restrict__ dW1, const float* __restrict__ db1,
    const float* __restrict__ dW2, const float* __restrict__ db2,
    const float* __restrict__ dW3, const float* __restrict__ db3,
    const float* __restrict__ kW3)
{
    extern __shared__ float sm[];
    float* s_W1 = sm + FG_W1;
    float* s_W2 = sm + FG_W2;
    float* s_W3 = sm + FG_W3;
    float* s_b1 = sm + FG_B1;
    float* s_b2 = sm + FG_B2;
    float* s_b3 = sm + FG_B3;
    float* s_kw = sm + FG_KW;
    float* s_x  = sm + FG_X;     // [8][128]
    float* s_h1 = sm + FG_H1;    // [8][32]
    float* s_h2 = sm + FG_H2;    // [8][16]
    float* s_f  = sm + FG_F;     // [8][32]

    int tid = threadIdx.x;
    // stage weights (vectorized)
    for (int q = tid; q < 992; q += 256)
        ((float4*)s_W1)[q] = ((const float4*)dW1)[q];
    for (int q = tid; q < 512; q += 256) s_W2[q] = dW2[q];
    for (int q = tid; q < 512; q += 256) s_W3[q] = dW3[q];
    if (tid < 32) s_b1[tid] = db1[tid];
    if (tid < 16) s_b2[tid] = db2[tid];
    if (tid < 32) s_b3[tid] = db3[tid];
    {
        const float4* kw4 = (const float4*)kW3;
        for (int q = tid; q < 2048; q += 256) {
            float4 v = kw4[q];
            int h = q >> 7;              // 128 float4 per h-row
            int rem = q & 127;
            int c = rem >> 2;
            int d4 = (rem & 3) << 2;
            *(float4*)(s_kw + c * 264 + h * 16 + d4) = v;
        }
    }

    int warp = tid >> 5, lane = tid & 31;
    int row = blockIdx.x * 8 + warp;
    int b = row / PP;

    const float* fb = feature + b * 64;
    const float* pr = pe + row * 60;
    float* xr = s_x + warp * 128;
    xr[lane]      = fb[lane];
    xr[32 + lane] = fb[32 + lane];
    xr[64 + lane] = pr[lane];
    if (lane < 28) xr[96 + lane] = pr[32 + lane];
    __syncthreads();

    // h1[32]
    {
        const float4* x4 = (const float4*)xr;
        float a0 = s_b1[lane], a1 = 0.f, a2 = 0.f, a3 = 0.f;
        #pragma unroll
        for (int k4 = 0; k4 < 31; k4++) {
            float4 xv = x4[k4];
            int k = k4 * 4;
            a0 = fmaf(xv.x, s_W1[(k)     * 32 + lane], a0);
            a1 = fmaf(xv.y, s_W1[(k + 1) * 32 + lane], a1);
            a2 = fmaf(xv.z, s_W1[(k + 2) * 32 + lane], a2);
            a3 = fmaf(xv.w, s_W1[(k + 3) * 32 + lane], a3);
        }
        s_h1[warp * 32 + lane] = fmaxf((a0 + a1) + (a2 + a3), 0.f);
    }
    __syncwarp();
    // h2[16]
    if (lane < 16) {
        float a0 = s_b2[lane], a1 = 0.f;
        #pragma unroll
        for (int k = 0; k < 32; k += 2) {
            a0 = fmaf(s_h1[warp * 32 + k],     s_W2[(k)     * 16 + lane], a0);
            a1 = fmaf(s_h1[warp * 32 + k + 1], s_W2[(k + 1) * 16 + lane], a1);
        }
        s_h2[warp * 16 + lane] = fmaxf(a0 + a1, 0.f);
    }
    __syncwarp();
    // feat[32]
    {
        float a0 = s_b3[lane], a1 = 0.f;
        #pragma unroll
        for (int k = 0; k < 16; k += 2) {
            a0 = fmaf(s_h2[warp * 16 + k],     s_W3[(k)     * 32 + lane], a0);
            a1 = fmaf(s_h2[warp * 16 + k + 1], s_W3[(k + 1) * 32 + lane], a1);
        }
        float f = fmaxf(a0 + a1, 0.f);
        s_f[warp * 32 + lane] = f;
        g_feat[row * 32 + lane] = f;
    }
    __syncthreads();

    // G: kw hoisted to registers (row-invariant), feat read as broadcast float4
    int hd = tid;
    float kw[32];
    #pragma unroll
    for (int c = 0; c < 32; c++) kw[c] = s_kw[c * 264 + hd];
    int r0 = blockIdx.x * 8;
    #pragma unroll 1
    for (int r = 0; r < 8; r++) {
        const float4* fr4 = (const float4*)(s_f + r * 32);
        float a0 = 0.f, a1 = 0.f, a2 = 0.f, a3 = 0.f;
        #pragma unroll
        for (int c4 = 0; c4 < 8; c4++) {
            float4 f = fr4[c4];
            a0 = fmaf(f.x, kw[c4 * 4 + 0], a0);
            a1 = fmaf(f.y, kw[c4 * 4 + 1], a1);
            a2 = fmaf(f.z, kw[c4 * 4 + 2], a2);
            a3 = fmaf(f.w, kw[c4 * 4 + 3], a3);
        }
        g_G[(r0 + r) * 256 + hd] = (a0 + a1) + (a2 + a3);
    }
}

// ---------------------------------------------------------------------------
// Kernel B: Sbias[b,d] = sum_c (sum_j feat[b,j,c]) * kb3[c*16+d]
// ---------------------------------------------------------------------------
__global__ __launch_bounds__(256) void sbias_kernel(const float* __restrict__ kb3)
{
    __shared__ float s_p[8][32];
    __shared__ float s_fs[32];
    int b = blockIdx.x;
    int tid = threadIdx.x;
    int c = tid & 31, grp = tid >> 5;
    float s = 0.f;
    for (int j = grp; j < PP; j += 8)
        s += g_feat[(b * PP + j) * 32 + c];
    s_p[grp][c] = s;
    __syncthreads();
    if (tid < 32) {
        float t = 0.f;
        #pragma unroll
        for (int g = 0; g < 8; g++) t += s_p[g][tid];
        s_fs[tid] = t;
    }
    __syncthreads();
    if (tid < 16) {
        float sb = 0.f;
        #pragma unroll
        for (int k = 0; k < 32; k++)
            sb = fmaf(s_fs[k], __ldg(kb3 + k * 16 + tid), sb);
        g_Sbias[b * 16 + tid] = sb;
    }
}

// ---------------------------------------------------------------------------
// Kernel C (hot): partial[b,i,d] += sum_{j in half,h} k2[i,j,h]*G[j,h,d]
// Grid = BB*NIT*2 (b, 7-row i-tile, j-half). 224 threads / 7 warps.
// j-half = 98 j's, processed in 7 tiles of 14.
// Contraction: warp w owns jj in {2w, 2w+1}; lane = (g = h-half, d); thread
// holds G[jj, g*8..g*8+7, d] in 8 regs, reused across 7 i-accumulators.
// ---------------------------------------------------------------------------
__global__ __launch_bounds__(224) void pair_kernel(
    const float* __restrict__ coords,
    const float* __restrict__ kW1, const float* __restrict__ kb1,
    const float* __restrict__ kW2, const float* __restrict__ kb2)
{
    extern __shared__ float sm[];
    float* s_k2  = sm;                           // IT*JT*K2P = 1960
    float* s_G   = s_k2 + IT * JT * K2P;         // JT*256    = 3584
    float* s_w   = s_G + JT * 256;               // 176
    float* s_ci  = s_w + 176;                    // 24
    float* s_cj  = s_ci + 24;                    // 48
    float* s_red = s_cj + 48;                    // 7*224 = 1568

    int tid = threadIdx.x;
    int bx = blockIdx.x;
    int b = bx / (NIT * 2);
    int rem = bx % (NIT * 2);
    int itile = rem >> 1;
    int jh = rem & 1;
    int i0 = itile * IT;
    int jbase = jh * (NT * JT);    // 0 or 98

    if (tid < 176) {
        float v;
        if (tid < 24)       v = kW1[tid];
        else if (tid < 32)  v = kb1[tid - 24];
        else if (tid < 160) v = kW2[tid - 32];
        else                v = kb2[tid - 160];
        s_w[tid] = v;
    }
    if (tid < IT * 3) s_ci[tid] = coords[(b * PP + i0) * 3 + tid];

    int w = tid >> 5, lane = tid & 31;
    int g = lane >> 4, d = lane & 15;

    float acc[IT];
    #pragma unroll
    for (int t = 0; t < IT; t++) acc[t] = 0.f;

    const float4* w2 = (const float4*)(s_w + 32);
    const float4* b2 = (const float4*)(s_w + 160);

    for (int tt = 0; tt < NT; tt++) {
        int j0 = jbase + tt * JT;
        __syncthreads();   // prior contraction done / initial loads done

        // stage G tile + j coords
        {
            const float4* src = (const float4*)(g_G + (b * PP + j0) * 256);
            float4* dst = (float4*)s_G;
            for (int q = tid; q < JT * 64; q += 224) dst[q] = src[q];
            if (tid < JT * 3) s_cj[tid] = coords[(b * PP + j0) * 3 + tid];
        }
        __syncthreads();   // staged before pair MLP reads

        // pair MLP: 98 pairs over 224 threads (tid < 98 active)
        if (tid < IT * JT) {
            int q = tid;
            int ii = q / JT;
            int jj = q - ii * JT;
            float r0 = s_cj[jj * 3 + 0] - s_ci[ii * 3 + 0];
            float r1 = s_cj[jj * 3 + 1] - s_ci[ii * 3 + 1];
            float r2 = s_cj[jj * 3 + 2] - s_ci[ii * 3 + 2];

            float a1[8];
            #pragma unroll
            for (int n = 0; n < 8; n++) {
                float a = s_w[24 + n];
                a = fmaf(r0, s_w[n], a);
                a = fmaf(r1, s_w[8 + n], a);
                a = fmaf(r2, s_w[16 + n], a);
                a1[n] = fmaxf(a, 0.f);
            }
            float a2[16];
            {
                float4 v0 = b2[0], v1 = b2[1], v2 = b2[2], v3 = b2[3];
                a2[0]=v0.x; a2[1]=v0.y; a2[2]=v0.z; a2[3]=v0.w;
                a2[4]=v1.x; a2[5]=v1.y; a2[6]=v1.z; a2[7]=v1.w;
                a2[8]=v2.x; a2[9]=v2.y; a2[10]=v2.z; a2[11]=v2.w;
                a2[12]=v3.x; a2[13]=v3.y; a2[14]=v3.z; a2[15]=v3.w;
            }
            #pragma unroll
            for (int k = 0; k < 8; k++) {
                float a = a1[k];
                #pragma unroll
                for (int n4 = 0; n4 < 4; n4++) {
                    float4 wv = w2[k * 4 + n4];
                    a2[n4*4+0] = fmaf(a, wv.x, a2[n4*4+0]);
                    a2[n4*4+1] = fmaf(a, wv.y, a2[n4*4+1]);
                    a2[n4*4+2] = fmaf(a, wv.z, a2[n4*4+2]);
                    a2[n4*4+3] = fmaf(a, wv.w, a2[n4*4+3]);
                }
            }
            float4* dst = (float4*)(s_k2 + q * K2P);
            #pragma unroll
            for (int n4 = 0; n4 < 4; n4++) {
                float4 v;
                v.x = fmaxf(a2[n4*4+0], 0.f);
                v.y = fmaxf(a2[n4*4+1], 0.f);
                v.z = fmaxf(a2[n4*4+2], 0.f);
                v.w = fmaxf(a2[n4*4+3], 0.f);
                dst[n4] = v;
            }
        }
        __syncthreads();

        // contraction: warp w handles jj = 2w, 2w+1
        #pragma unroll
        for (int m = 0; m < 2; m++) {
            int jj = w * 2 + m;
            const float* Gj = s_G + jj * 256 + g * 128 + d;
            float Gv[8];
            #pragma unroll
            for (int hh = 0; hh < 8; hh++) Gv[hh] = Gj[hh * 16];
            #pragma unroll
            for (int t = 0; t < IT; t++) {
                const float4* k4 = (const float4*)(s_k2 + (t * JT + jj) * K2P + g * 8);
                float4 ka = k4[0], kb = k4[1];
                float a = acc[t];
                a = fmaf(ka.x, Gv[0], a);
                a = fmaf(ka.y, Gv[1], a);
                a = fmaf(ka.z, Gv[2], a);
                a = fmaf(ka.w, Gv[3], a);
                a = fmaf(kb.x, Gv[4], a);
                a = fmaf(kb.y, Gv[5], a);
                a = fmaf(kb.z, Gv[6], a);
                a = fmaf(kb.w, Gv[7], a);
                acc[t] = a;
            }
        }
    }

    // cross-warp (+ h-half) reduction -> g_part
    __syncthreads();
    #pragma unroll
    for (int t = 0; t < IT; t++)
        s_red[w * 224 + g * 112 + t * 16 + d] = acc[t];
    __syncthreads();
    if (tid < IT * 16) {
        int i = tid >> 4;
        int dd = tid & 15;
        float s = 0.f;
        #pragma unroll
        for (int ww = 0; ww < 7; ww++) {
            s += s_red[ww * 224 + tid];
            s += s_red[ww * 224 + 112 + tid];
        }
        g_part[jh * (ROWS * 16) + (b * PP + i0 + i) * 16 + dd] = s;
    }
}

// ---------------------------------------------------------------------------
// Kernel D: out = relu(part0 + part1 + Sbias)
// ---------------------------------------------------------------------------
__global__ __launch_bounds__(256) void combine_kernel(float* __restrict__ out)
{
    int idx = blockIdx.x * 256 + threadIdx.x;
    if (idx < ROWS * 16) {
        int b = idx / (PP * 16);
        int d = idx & 15;
        float v = g_part[idx] + g_part[ROWS * 16 + idx] + g_Sbias[b * 16 + d];
        out[idx] = fmaxf(v, 0.f);
    }
}

// ---------------------------------------------------------------------------
extern "C" void kernel_launch(void* const* d_in, const int* in_sizes, int n_in,
                              void* d_out, int out_size)
{
    const float* feature = (const float*)d_in[0];
    const float* pe      = (const float*)d_in[1];
    const float* coords  = (const float*)d_in[2];
    const float* dW1 = (const float*)d_in[3];
    const float* db1 = (const float*)d_in[4];
    const float* dW2 = (const float*)d_in[5];
    const float* db2 = (const float*)d_in[6];
    const float* dW3 = (const float*)d_in[7];
    const float* db3 = (const float*)d_in[8];
    const float* kW1 = (const float*)d_in[9];
    const float* kb1 = (const float*)d_in[10];
    const float* kW2 = (const float*)d_in[11];
    const float* kb2 = (const float*)d_in[12];
    const float* kW3 = (const float*)d_in[13];
    const float* kb3 = (const float*)d_in[14];
    float* out = (float*)d_out;

    const int smemFG = FG_TOT * (int)sizeof(float);
    const int smemP  = (IT * JT * K2P + JT * 256 + 176 + 24 + 48 + 7 * 224)
                       * (int)sizeof(float);
    static bool attr_set = false;
    if (!attr_set) {
        cudaFuncSetAttribute(feat_G_kernel, cudaFuncAttributeMaxDynamicSharedMemorySize, smemFG);
        cudaFuncSetAttribute(pair_kernel, cudaFuncAttributeMaxDynamicSharedMemorySize, smemP);
        attr_set = true;
    }

    feat_G_kernel<<<196, 256, smemFG>>>(feature, pe, dW1, db1, dW2, db2, dW3, db3, kW3);
    sbias_kernel<<<BB, 256>>>(kb3);
    pair_kernel<<<BB * NIT * 2, 224, smemP>>>(coords, kW1, kb1, kW2, kb2);
    combine_kernel<<<(ROWS * 16 + 255) / 256, 256>>>(out);
}

// round 7
// speedup vs baseline: 1.0620x; 1.0620x over previous
#include <cuda_runtime.h>

#define BB 8
#define PP 196
#define ROWS (BB*PP)        // 1568
#define IT 7
#define NIT 28              // i-tiles per batch
#define JSEV 7              // j-sevenths
#define JT 28               // j's per pair job
#define K2P 20              // padded pitch for k2 rows (16 used)
#define NPAIR (BB*NIT*JSEV) // 1568
#define NJOBS (8 + NPAIR)   // 1576

// Scratch (allocation-free rule: __device__ globals)
__device__ __align__(16) float g_G[ROWS * 256];
__device__ __align__(16) float g_feat[ROWS * 32];
__device__ __align__(16) float g_part[JSEV * ROWS * 16];
__device__ float g_Sbias[BB * 16];
__device__ unsigned g_cnt = 0;
__device__ unsigned g_gen = 0;

// Phase-1 smem layout (floats)
#define FG_W1   0                    // 124*32 = 3968
#define FG_W2   (FG_W1 + 3968)       // 512
#define FG_W3   (FG_W2 + 512)        // 512
#define FG_B1   (FG_W3 + 512)        // 32
#define FG_B2   (FG_B1 + 32)         // 16
#define FG_B3   (FG_B2 + 16)         // 32
#define FG_KW   (FG_B3 + 32)         // 32*264 = 8448
#define FG_X    (FG_KW + 8448)       // 8*128 = 1024
#define FG_H1   (FG_X + 1024)        // 256
#define FG_H2   (FG_H1 + 256)        // 128
#define FG_F    (FG_H2 + 128)        // 256
#define FG_TOT  (FG_F + 256)         // 15184 floats = 60736 B

// Phase-2 smem layout (floats, aliases phase-1 region)
#define P2_K2   0                    // IT*JT*K2P = 3920
#define P2_G    (P2_K2 + 3920)       // JT*256 = 7168  (16B aligned: 3920*4%16==0)
#define P2_W    (P2_G + 7168)        // 176
#define P2_CI   (P2_W + 176)         // 24
#define P2_CJ   (P2_CI + 24)         // 88
#define P2_RED  (P2_CJ + 88)         // 8*224 = 1792
#define P2_TOT  (P2_RED + 1792)      // 13168 < FG_TOT

__device__ __forceinline__ void grid_barrier(int nb)
{
    __syncthreads();
    if (threadIdx.x == 0) {
        __threadfence();
        unsigned gen = atomicAdd(&g_gen, 0u);
        if (atomicAdd(&g_cnt, 1u) == (unsigned)(nb - 1)) {
            g_cnt = 0;
            __threadfence();
            atomicAdd(&g_gen, 1u);
        } else {
            while (atomicAdd(&g_gen, 0u) == gen) { __nanosleep(32); }
        }
        __threadfence();
    }
    __syncthreads();
}

__global__ __launch_bounds__(256) void fused_kernel(
    const float* __restrict__ feature, const float* __restrict__ pe,
    const float* __restrict__ coords,
    const float* __restrict__ dW1, const float* __restrict__ db1,
    const float* __restrict__ dW2, const float* __restrict__ db2,
    const float* __restrict__ dW3, const float* __restrict__ db3,
    const float* __restrict__ kW1, const float* __restrict__ kb1,
    const float* __restrict__ kW2, const float* __restrict__ kb2,
    const float* __restrict__ kW3, const float* __restrict__ kb3,
    float* __restrict__ out, int NB)
{
    extern __shared__ float sm[];
    int tid = threadIdx.x;
    int warp = tid >> 5, lane = tid & 31;

    // ===================== Phase 1: feat + G =====================
    if (blockIdx.x < 196) {
        float* s_W1 = sm + FG_W1;
        float* s_W2 = sm + FG_W2;
        float* s_W3 = sm + FG_W3;
        float* s_b1 = sm + FG_B1;
        float* s_b2 = sm + FG_B2;
        float* s_b3 = sm + FG_B3;
        float* s_kw = sm + FG_KW;
        float* s_x  = sm + FG_X;
        float* s_h1 = sm + FG_H1;
        float* s_h2 = sm + FG_H2;
        float* s_f  = sm + FG_F;

        for (int q = tid; q < 992; q += 256)
            ((float4*)s_W1)[q] = ((const float4*)dW1)[q];
        for (int q = tid; q < 512; q += 256) s_W2[q] = dW2[q];
        for (int q = tid; q < 512; q += 256) s_W3[q] = dW3[q];
        if (tid < 32) s_b1[tid] = db1[tid];
        if (tid < 16) s_b2[tid] = db2[tid];
        if (tid < 32) s_b3[tid] = db3[tid];
        {
            const float4* kw4 = (const float4*)kW3;
            for (int q = tid; q < 2048; q += 256) {
                float4 v = kw4[q];
                int h = q >> 7;
                int rem = q & 127;
                int c = rem >> 2;
                int d4 = (rem & 3) << 2;
                *(float4*)(s_kw + c * 264 + h * 16 + d4) = v;
            }
        }
        __syncthreads();

        // row-invariant kW3 column in registers
        float kw[32];
        #pragma unroll
        for (int c = 0; c < 32; c++) kw[c] = s_kw[c * 264 + tid];

        for (int tile = blockIdx.x; tile < 196; tile += NB) {
            int row = tile * 8 + warp;
            int b = row / PP;
            const float* fb = feature + b * 64;
            const float* pr = pe + row * 60;
            float* xr = s_x + warp * 128;
            xr[lane]      = fb[lane];
            xr[32 + lane] = fb[32 + lane];
            xr[64 + lane] = pr[lane];
            if (lane < 28) xr[96 + lane] = pr[32 + lane];
            __syncwarp();

            // h1
            {
                const float4* x4 = (const float4*)xr;
                float a0 = s_b1[lane], a1 = 0.f, a2 = 0.f, a3 = 0.f;
                #pragma unroll
                for (int k4 = 0; k4 < 31; k4++) {
                    float4 xv = x4[k4];
                    int k = k4 * 4;
                    a0 = fmaf(xv.x, s_W1[(k)     * 32 + lane], a0);
                    a1 = fmaf(xv.y, s_W1[(k + 1) * 32 + lane], a1);
                    a2 = fmaf(xv.z, s_W1[(k + 2) * 32 + lane], a2);
                    a3 = fmaf(xv.w, s_W1[(k + 3) * 32 + lane], a3);
                }
                s_h1[warp * 32 + lane] = fmaxf((a0 + a1) + (a2 + a3), 0.f);
            }
            __syncwarp();
            if (lane < 16) {
                float a0 = s_b2[lane], a1 = 0.f;
                #pragma unroll
                for (int k = 0; k < 32; k += 2) {
                    a0 = fmaf(s_h1[warp * 32 + k],     s_W2[(k)     * 16 + lane], a0);
                    a1 = fmaf(s_h1[warp * 32 + k + 1], s_W2[(k + 1) * 16 + lane], a1);
                }
                s_h2[warp * 16 + lane] = fmaxf(a0 + a1, 0.f);
            }
            __syncwarp();
            {
                float a0 = s_b3[lane], a1 = 0.f;
                #pragma unroll
                for (int k = 0; k < 16; k += 2) {
                    a0 = fmaf(s_h2[warp * 16 + k],     s_W3[(k)     * 32 + lane], a0);
                    a1 = fmaf(s_h2[warp * 16 + k + 1], s_W3[(k + 1) * 32 + lane], a1);
                }
                float f = fmaxf(a0 + a1, 0.f);
                s_f[warp * 32 + lane] = f;
                g_feat[row * 32 + lane] = f;
            }
            __syncthreads();   // s_f complete for all 8 rows

            int r0 = tile * 8;
            #pragma unroll 1
            for (int r = 0; r < 8; r++) {
                const float4* fr4 = (const float4*)(s_f + r * 32);
                float a0 = 0.f, a1 = 0.f, a2 = 0.f, a3 = 0.f;
                #pragma unroll
                for (int c4 = 0; c4 < 8; c4++) {
                    float4 f = fr4[c4];
                    a0 = fmaf(f.x, kw[c4 * 4 + 0], a0);
                    a1 = fmaf(f.y, kw[c4 * 4 + 1], a1);
                    a2 = fmaf(f.z, kw[c4 * 4 + 2], a2);
                    a3 = fmaf(f.w, kw[c4 * 4 + 3], a3);
                }
                g_G[(r0 + r) * 256 + tid] = (a0 + a1) + (a2 + a3);
            }
            __syncthreads();   // before next tile overwrites s_x/s_f
        }
    }

    grid_barrier(NB);

    // ===================== Phase 2: sbias + pair partials =====================
    {
        float* s_k2  = sm + P2_K2;
        float* s_G   = sm + P2_G;
        float* s_w   = sm + P2_W;
        float* s_ci  = sm + P2_CI;
        float* s_cj  = sm + P2_CJ;
        float* s_red = sm + P2_RED;
        int g = lane >> 4, d = lane & 15;

        for (int job = blockIdx.x; job < NJOBS; job += NB) {
            __syncthreads();   // smem reuse fence between jobs
            if (job < 8) {
                // sbias for batch b = job
                int b = job;
                int c = tid & 31, grp = tid >> 5;
                float s = 0.f;
                for (int j = grp; j < PP; j += 8)
                    s += __ldcg(&g_feat[(b * PP + j) * 32 + c]);
                s_red[grp * 32 + c] = s;
                __syncthreads();
                if (tid < 16) {
                    float sb = 0.f;
                    #pragma unroll
                    for (int k = 0; k < 32; k++) {
                        float fs = s_red[k] + s_red[32 + k] + s_red[64 + k] + s_red[96 + k]
                                 + s_red[128 + k] + s_red[160 + k] + s_red[192 + k] + s_red[224 + k];
                        sb = fmaf(fs, __ldg(kb3 + k * 16 + tid), sb);
                    }
                    g_Sbias[b * 16 + tid] = sb;
                }
                continue;
            }
            int pj = job - 8;
            int b = pj / (NIT * JSEV);
            int rem = pj % (NIT * JSEV);
            int itile = rem / JSEV;
            int jsev = rem % JSEV;
            int i0 = itile * IT;
            int j0 = jsev * JT;

            // stage weights/coords/G tile
            if (tid < 176) {
                float v;
                if (tid < 24)       v = kW1[tid];
                else if (tid < 32)  v = kb1[tid - 24];
                else if (tid < 160) v = kW2[tid - 32];
                else                v = kb2[tid - 160];
                s_w[tid] = v;
            }
            if (tid < IT * 3) s_ci[tid] = __ldg(&coords[(b * PP + i0) * 3 + tid]);
            if (tid < JT * 3) s_cj[tid] = __ldg(&coords[(b * PP + j0) * 3 + tid]);
            {
                const float4* src = (const float4*)(g_G + (b * PP + j0) * 256);
                float4* dst = (float4*)s_G;
                for (int q = tid; q < JT * 64; q += 256) dst[q] = __ldcg(&src[q]);
            }
            __syncthreads();

            // pair MLP: 196 pairs, tid < 196 each does one
            if (tid < IT * JT) {
                int ii = tid / JT;
                int jj = tid - ii * JT;
                float r0 = s_cj[jj * 3 + 0] - s_ci[ii * 3 + 0];
                float r1 = s_cj[jj * 3 + 1] - s_ci[ii * 3 + 1];
                float r2 = s_cj[jj * 3 + 2] - s_ci[ii * 3 + 2];

                float a1[8];
                #pragma unroll
                for (int n = 0; n < 8; n++) {
                    float a = s_w[24 + n];
                    a = fmaf(r0, s_w[n], a);
                    a = fmaf(r1, s_w[8 + n], a);
                    a = fmaf(r2, s_w[16 + n], a);
                    a1[n] = fmaxf(a, 0.f);
                }
                const float4* w2 = (const float4*)(s_w + 32);
                const float4* b2 = (const float4*)(s_w + 160);
                float a2[16];
                {
                    float4 v0 = b2[0], v1 = b2[1], v2 = b2[2], v3 = b2[3];
                    a2[0]=v0.x; a2[1]=v0.y; a2[2]=v0.z; a2[3]=v0.w;
                    a2[4]=v1.x; a2[5]=v1.y; a2[6]=v1.z; a2[7]=v1.w;
                    a2[8]=v2.x; a2[9]=v2.y; a2[10]=v2.z; a2[11]=v2.w;
                    a2[12]=v3.x; a2[13]=v3.y; a2[14]=v3.z; a2[15]=v3.w;
                }
                #pragma unroll
                for (int k = 0; k < 8; k++) {
                    float a = a1[k];
                    #pragma unroll
                    for (int n4 = 0; n4 < 4; n4++) {
                        float4 wv = w2[k * 4 + n4];
                        a2[n4*4+0] = fmaf(a, wv.x, a2[n4*4+0]);
                        a2[n4*4+1] = fmaf(a, wv.y, a2[n4*4+1]);
                        a2[n4*4+2] = fmaf(a, wv.z, a2[n4*4+2]);
                        a2[n4*4+3] = fmaf(a, wv.w, a2[n4*4+3]);
                    }
                }
                float4* dst = (float4*)(s_k2 + tid * K2P);
                #pragma unroll
                for (int n4 = 0; n4 < 4; n4++) {
                    float4 v;
                    v.x = fmaxf(a2[n4*4+0], 0.f);
                    v.y = fmaxf(a2[n4*4+1], 0.f);
                    v.z = fmaxf(a2[n4*4+2], 0.f);
                    v.w = fmaxf(a2[n4*4+3], 0.f);
                    dst[n4] = v;
                }
            }
            __syncthreads();

            // contraction: warp w handles jj = w, w+8, w+16, w+24 (<28)
            float acc[IT];
            #pragma unroll
            for (int t = 0; t < IT; t++) acc[t] = 0.f;
            for (int jj = warp; jj < JT; jj += 8) {
                const float* Gj = s_G + jj * 256 + g * 128 + d;
                float Gv[8];
                #pragma unroll
                for (int hh = 0; hh < 8; hh++) Gv[hh] = Gj[hh * 16];
                #pragma unroll
                for (int t = 0; t < IT; t++) {
                    const float4* k4 = (const float4*)(s_k2 + (t * JT + jj) * K2P + g * 8);
                    float4 ka = k4[0], kb = k4[1];
                    float a = acc[t];
                    a = fmaf(ka.x, Gv[0], a);
                    a = fmaf(ka.y, Gv[1], a);
                    a = fmaf(ka.z, Gv[2], a);
                    a = fmaf(ka.w, Gv[3], a);
                    a = fmaf(kb.x, Gv[4], a);
                    a = fmaf(kb.y, Gv[5], a);
                    a = fmaf(kb.z, Gv[6], a);
                    a = fmaf(kb.w, Gv[7], a);
                    acc[t] = a;
                }
            }
            __syncthreads();   // s_red free (sbias path also used it)
            #pragma unroll
            for (int t = 0; t < IT; t++)
                s_red[warp * 224 + g * 112 + t * 16 + d] = acc[t];
            __syncthreads();
            if (tid < IT * 16) {
                float s = 0.f;
                #pragma unroll
                for (int ww = 0; ww < 8; ww++)
                    s += s_red[ww * 224 + tid] + s_red[ww * 224 + 112 + tid];
                g_part[jsev * (ROWS * 16) + (b * PP + i0) * 16 + tid] = s;
            }
        }
    }

    grid_barrier(NB);

    // ===================== Phase 3: combine =====================
    for (int idx = blockIdx.x * 256 + tid; idx < ROWS * 16; idx += NB * 256) {
        int b = idx / (PP * 16);
        float v = __ldcg(&g_Sbias[b * 16 + (idx & 15)]);
        #pragma unroll
        for (int q = 0; q < JSEV; q++)
            v += __ldcg(&g_part[q * (ROWS * 16) + idx]);
        out[idx] = fmaxf(v, 0.f);
    }
}

// ---------------------------------------------------------------------------
extern "C" void kernel_launch(void* const* d_in, const int* in_sizes, int n_in,
                              void* d_out, int out_size)
{
    const float* feature = (const float*)d_in[0];
    const float* pe      = (const float*)d_in[1];
    const float* coords  = (const float*)d_in[2];
    const float* dW1 = (const float*)d_in[3];
    const float* db1 = (const float*)d_in[4];
    const float* dW2 = (const float*)d_in[5];
    const float* db2 = (const float*)d_in[6];
    const float* dW3 = (const float*)d_in[7];
    const float* db3 = (const float*)d_in[8];
    const float* kW1 = (const float*)d_in[9];
    const float* kb1 = (const float*)d_in[10];
    const float* kW2 = (const float*)d_in[11];
    const float* kb2 = (const float*)d_in[12];
    const float* kW3 = (const float*)d_in[13];
    const float* kb3 = (const float*)d_in[14];
    float* out = (float*)d_out;

    const int smemB = FG_TOT * (int)sizeof(float);   // 60736 B
    cudaFuncSetAttribute(fused_kernel, cudaFuncAttributeMaxDynamicSharedMemorySize, smemB);

    int dev = 0;
    cudaGetDevice(&dev);
    int sms = 0;
    cudaDeviceGetAttribute(&sms, cudaDevAttrMultiProcessorCount, dev);
    int maxB = 0;
    cudaOccupancyMaxActiveBlocksPerMultiprocessor(&maxB, fused_kernel, 256, smemB);
    if (maxB < 1) maxB = 1;
    int NB = sms * maxB;
    if (NB > NJOBS) NB = NJOBS;

    fused_kernel<<<NB, 256, smemB>>>(feature, pe, coords,
                                     dW1, db1, dW2, db2, dW3, db3,
                                     kW1, kb1, kW2, kb2, kW3, kb3,
                                     out, NB);
}

// round 9
// speedup vs baseline: 1.2074x; 1.1370x over previous
#include <cuda_runtime.h>

#define BB 8
#define PP 196
#define ROWS (BB*PP)        // 1568
#define IT 7
#define NIT 28              // i-tiles per batch
#define JSEV 7              // j-sevenths
#define JT 28               // j's per pair job
#define K2P 20              // padded pitch for k2 rows (16 used)
#define NPAIR (BB*NIT*JSEV) // 1568
#define NJOBS (8 + NPAIR)   // 1576
#define NTILE1 392          // phase-1 tiles (4 rows each)

// Scratch (allocation-free rule: __device__ globals)
__device__ __align__(16) float g_G[ROWS * 256];
__device__ __align__(16) float g_feat[ROWS * 32];
__device__ __align__(16) float g_part[JSEV * ROWS * 16];
__device__ float g_Sbias[BB * 16];
__device__ unsigned g_cnt = 0;
__device__ unsigned g_gen = 0;

// Phase-1 smem layout (floats) -- 4 decode rows per tile
#define FG_W1   0                    // 124*32 = 3968
#define FG_W2   (FG_W1 + 3968)       // 512
#define FG_W3   (FG_W2 + 512)        // 512
#define FG_B1   (FG_W3 + 512)        // 32
#define FG_B2   (FG_B1 + 32)         // 16
#define FG_B3   (FG_B2 + 16)         // 32
#define FG_X    (FG_B3 + 32)         // 4*128 = 512 (16B aligned: 5072*4%16==0)
#define FG_H1   (FG_X + 512)         // 4*32 = 128
#define FG_H2   (FG_H1 + 128)        // 4*16 = 64
#define FG_F    (FG_H2 + 64)         // 4*32 = 128 (16B aligned)
#define FG_TOT  (FG_F + 128)         // 5904 floats

// Phase-2 smem layout (floats, aliases phase-1 region)
#define P2_K2   0                    // IT*JT*K2P = 3920
#define P2_W    (P2_K2 + 3920)       // 176
#define P2_CI   (P2_W + 176)         // 24
#define P2_CJ   (P2_CI + 24)         // 88
#define P2_RED  (P2_CJ + 88)         // 8*224 = 1792
#define P2_TOT  (P2_RED + 1792)      // 6000 floats

#define SM_TOT  (P2_TOT > FG_TOT ? P2_TOT : FG_TOT)   // 6000 floats = 24000 B

__device__ __forceinline__ void grid_barrier(int nb)
{
    __syncthreads();
    if (threadIdx.x == 0) {
        __threadfence();
        unsigned gen = atomicAdd(&g_gen, 0u);
        if (atomicAdd(&g_cnt, 1u) == (unsigned)(nb - 1)) {
            g_cnt = 0;
            __threadfence();
            atomicAdd(&g_gen, 1u);
        } else {
            while (atomicAdd(&g_gen, 0u) == gen) { __nanosleep(32); }
        }
        __threadfence();
    }
    __syncthreads();
}

__global__ __launch_bounds__(256) void fused_kernel(
    const float* __restrict__ feature, const float* __restrict__ pe,
    const float* __restrict__ coords,
    const float* __restrict__ dW1, const float* __restrict__ db1,
    const float* __restrict__ dW2, const float* __restrict__ db2,
    const float* __restrict__ dW3, const float* __restrict__ db3,
    const float* __restrict__ kW1, const float* __restrict__ kb1,
    const float* __restrict__ kW2, const float* __restrict__ kb2,
    const float* __restrict__ kW3, const float* __restrict__ kb3,
    float* __restrict__ out, int NB)
{
    extern __shared__ float sm[];
    int tid = threadIdx.x;
    int warp = tid >> 5, lane = tid & 31;

    // ===================== Phase 1: feat + G =====================
    // kW3 column for this thread's hd=tid, straight from gmem (L2-shared).
    float kw[32];
    {
        const float* kp = kW3 + (tid >> 4) * 512 + (tid & 15);
        #pragma unroll
        for (int c = 0; c < 32; c++) kw[c] = __ldg(kp + c * 16);
    }

    if (blockIdx.x < NTILE1) {
        float* s_W1 = sm + FG_W1;
        float* s_W2 = sm + FG_W2;
        float* s_W3 = sm + FG_W3;
        float* s_b1 = sm + FG_B1;
        float* s_b2 = sm + FG_B2;
        float* s_b3 = sm + FG_B3;
        float* s_x  = sm + FG_X;     // [4][128]
        float* s_h1 = sm + FG_H1;    // [4][32]
        float* s_h2 = sm + FG_H2;    // [4][16]
        float* s_f  = sm + FG_F;     // [4][32]

        for (int q = tid; q < 992; q += 256)
            ((float4*)s_W1)[q] = ((const float4*)dW1)[q];
        for (int q = tid; q < 512; q += 256) s_W2[q] = dW2[q];
        for (int q = tid; q < 512; q += 256) s_W3[q] = dW3[q];
        if (tid < 32) s_b1[tid] = db1[tid];
        else if (tid < 48) s_b2[tid - 32] = db2[tid - 32];
        else if (tid < 80) s_b3[tid - 48] = db3[tid - 48];

        for (int tile = blockIdx.x; tile < NTILE1; tile += NB) {
            int row = tile * 4 + warp;
            if (warp < 4) {
                int b = row / PP;
                const float* fb = feature + b * 64;
                const float* pr = pe + row * 60;
                float* xr = s_x + warp * 128;
                xr[lane]      = fb[lane];
                xr[32 + lane] = fb[32 + lane];
                xr[64 + lane] = pr[lane];
                if (lane < 28) xr[96 + lane] = pr[32 + lane];
            }
            __syncthreads();   // weights (first tile) + x staged

            if (warp < 4) {
                const float* xr = s_x + warp * 128;
                // h1
                {
                    const float4* x4 = (const float4*)xr;
                    float a0 = s_b1[lane], a1 = 0.f, a2 = 0.f, a3 = 0.f;
                    #pragma unroll
                    for (int k4 = 0; k4 < 31; k4++) {
                        float4 xv = x4[k4];
                        int k = k4 * 4;
                        a0 = fmaf(xv.x, s_W1[(k)     * 32 + lane], a0);
                        a1 = fmaf(xv.y, s_W1[(k + 1) * 32 + lane], a1);
                        a2 = fmaf(xv.z, s_W1[(k + 2) * 32 + lane], a2);
                        a3 = fmaf(xv.w, s_W1[(k + 3) * 32 + lane], a3);
                    }
                    s_h1[warp * 32 + lane] = fmaxf((a0 + a1) + (a2 + a3), 0.f);
                }
                __syncwarp();
                if (lane < 16) {
                    float a0 = s_b2[lane], a1 = 0.f;
                    #pragma unroll
                    for (int k = 0; k < 32; k += 2) {
                        a0 = fmaf(s_h1[warp * 32 + k],     s_W2[(k)     * 16 + lane], a0);
                        a1 = fmaf(s_h1[warp * 32 + k + 1], s_W2[(k + 1) * 16 + lane], a1);
                    }
                    s_h2[warp * 16 + lane] = fmaxf(a0 + a1, 0.f);
                }
                __syncwarp();
                {
                    float a0 = s_b3[lane], a1 = 0.f;
                    #pragma unroll
                    for (int k = 0; k < 16; k += 2) {
                        a0 = fmaf(s_h2[warp * 16 + k],     s_W3[(k)     * 32 + lane], a0);
                        a1 = fmaf(s_h2[warp * 16 + k + 1], s_W3[(k + 1) * 32 + lane], a1);
                    }
                    float f = fmaxf(a0 + a1, 0.f);
                    s_f[warp * 32 + lane] = f;
                    g_feat[row * 32 + lane] = f;
                }
            }
            __syncthreads();   // s_f complete

            int r0 = tile * 4;
            #pragma unroll
            for (int r = 0; r < 4; r++) {
                const float4* fr4 = (const float4*)(s_f + r * 32);
                float a0 = 0.f, a1 = 0.f, a2 = 0.f, a3 = 0.f;
                #pragma unroll
                for (int c4 = 0; c4 < 8; c4++) {
                    float4 f = fr4[c4];
                    a0 = fmaf(f.x, kw[c4 * 4 + 0], a0);
                    a1 = fmaf(f.y, kw[c4 * 4 + 1], a1);
                    a2 = fmaf(f.z, kw[c4 * 4 + 2], a2);
                    a3 = fmaf(f.w, kw[c4 * 4 + 3], a3);
                }
                g_G[(r0 + r) * 256 + tid] = (a0 + a1) + (a2 + a3);
            }
            __syncthreads();   // before next tile overwrites s_x/s_f
        }
    }

    grid_barrier(NB);

    // ===================== Phase 2: sbias + pair partials =====================
    {
        float* s_k2  = sm + P2_K2;
        float* s_w   = sm + P2_W;
        float* s_ci  = sm + P2_CI;
        float* s_cj  = sm + P2_CJ;
        float* s_red = sm + P2_RED;
        int g = lane >> 4, d = lane & 15;

        // stage pair-MLP weights once per block
        if (tid < 176) {
            float v;
            if (tid < 24)       v = kW1[tid];
            else if (tid < 32)  v = kb1[tid - 24];
            else if (tid < 160) v = kW2[tid - 32];
            else                v = kb2[tid - 160];
            s_w[tid] = v;
        }

        for (int job = blockIdx.x; job < NJOBS; job += NB) {
            if (job < 8) {
                __syncthreads();   // protect s_red reuse
                int b = job;
                int c = tid & 31, grp = tid >> 5;
                float s = 0.f;
                for (int j = grp; j < PP; j += 8)
                    s += __ldcg(&g_feat[(b * PP + j) * 32 + c]);
                s_red[grp * 32 + c] = s;
                __syncthreads();
                if (tid < 16) {
                    float sb = 0.f;
                    #pragma unroll
                    for (int k = 0; k < 32; k++) {
                        float fs = s_red[k] + s_red[32 + k] + s_red[64 + k] + s_red[96 + k]
                                 + s_red[128 + k] + s_red[160 + k] + s_red[192 + k] + s_red[224 + k];
                        sb = fmaf(fs, __ldg(kb3 + k * 16 + tid), sb);
                    }
                    g_Sbias[b * 16 + tid] = sb;
                }
                continue;
            }
            int pj = job - 8;
            int b = pj / (NIT * JSEV);
            int rem = pj % (NIT * JSEV);
            int itile = rem / JSEV;
            int jsev = rem % JSEV;
            int i0 = itile * IT;
            int j0 = jsev * JT;

            if (tid < IT * 3) s_ci[tid] = __ldg(&coords[(b * PP + i0) * 3 + tid]);
            if (tid < JT * 3) s_cj[tid] = __ldg(&coords[(b * PP + j0) * 3 + tid]);
            __syncthreads();   // ci/cj (and s_w on first job) visible

            // pair MLP: 196 pairs, tid < 196 each does one
            if (tid < IT * JT) {
                int ii = tid / JT;
                int jj = tid - ii * JT;
                float r0 = s_cj[jj * 3 + 0] - s_ci[ii * 3 + 0];
                float r1 = s_cj[jj * 3 + 1] - s_ci[ii * 3 + 1];
                float r2 = s_cj[jj * 3 + 2] - s_ci[ii * 3 + 2];

                float a1[8];
                #pragma unroll
                for (int n = 0; n < 8; n++) {
                    float a = s_w[24 + n];
                    a = fmaf(r0, s_w[n], a);
                    a = fmaf(r1, s_w[8 + n], a);
                    a = fmaf(r2, s_w[16 + n], a);
                    a1[n] = fmaxf(a, 0.f);
                }
                const float4* w2 = (const float4*)(s_w + 32);
                const float4* b2 = (const float4*)(s_w + 160);
                float a2[16];
                {
                    float4 v0 = b2[0], v1 = b2[1], v2 = b2[2], v3 = b2[3];
                    a2[0]=v0.x; a2[1]=v0.y; a2[2]=v0.z; a2[3]=v0.w;
                    a2[4]=v1.x; a2[5]=v1.y; a2[6]=v1.z; a2[7]=v1.w;
                    a2[8]=v2.x; a2[9]=v2.y; a2[10]=v2.z; a2[11]=v2.w;
                    a2[12]=v3.x; a2[13]=v3.y; a2[14]=v3.z; a2[15]=v3.w;
                }
                #pragma unroll
                for (int k = 0; k < 8; k++) {
                    float a = a1[k];
                    #pragma unroll
                    for (int n4 = 0; n4 < 4; n4++) {
                        float4 wv = w2[k * 4 + n4];
                        a2[n4*4+0] = fmaf(a, wv.x, a2[n4*4+0]);
                        a2[n4*4+1] = fmaf(a, wv.y, a2[n4*4+1]);
                        a2[n4*4+2] = fmaf(a, wv.z, a2[n4*4+2]);
                        a2[n4*4+3] = fmaf(a, wv.w, a2[n4*4+3]);
                    }
                }
                float4* dst = (float4*)(s_k2 + tid * K2P);
                #pragma unroll
                for (int n4 = 0; n4 < 4; n4++) {
                    float4 v;
                    v.x = fmaxf(a2[n4*4+0], 0.f);
                    v.y = fmaxf(a2[n4*4+1], 0.f);
                    v.z = fmaxf(a2[n4*4+2], 0.f);
                    v.w = fmaxf(a2[n4*4+3], 0.f);
                    dst[n4] = v;
                }
            }
            __syncthreads();

            // contraction: warp w handles jj = w, w+8, w+16, w+24 (<28).
            // G read directly from gmem (coalesced, read-only after barrier).
            float acc[IT];
            #pragma unroll
            for (int t = 0; t < IT; t++) acc[t] = 0.f;
            const float* Gbase = g_G + (b * PP + j0) * 256 + g * 128 + d;
            for (int jj = warp; jj < JT; jj += 8) {
                const float* Gj = Gbase + jj * 256;
                float Gv[8];
                #pragma unroll
                for (int hh = 0; hh < 8; hh++) Gv[hh] = __ldg(Gj + hh * 16);
                #pragma unroll
                for (int t = 0; t < IT; t++) {
                    const float4* k4 = (const float4*)(s_k2 + (t * JT + jj) * K2P + g * 8);
                    float4 ka = k4[0], kb = k4[1];
                    float a = acc[t];
                    a = fmaf(ka.x, Gv[0], a);
                    a = fmaf(ka.y, Gv[1], a);
                    a = fmaf(ka.z, Gv[2], a);
                    a = fmaf(ka.w, Gv[3], a);
                    a = fmaf(kb.x, Gv[4], a);
                    a = fmaf(kb.y, Gv[5], a);
                    a = fmaf(kb.z, Gv[6], a);
                    a = fmaf(kb.w, Gv[7], a);
                    acc[t] = a;
                }
            }
            __syncthreads();   // s_red free
            #pragma unroll
            for (int t = 0; t < IT; t++)
                s_red[warp * 224 + g * 112 + t * 16 + d] = acc[t];
            __syncthreads();
            if (tid < IT * 16) {
                float s = 0.f;
                #pragma unroll
                for (int ww = 0; ww < 8; ww++)
                    s += s_red[ww * 224 + tid] + s_red[ww * 224 + 112 + tid];
                g_part[jsev * (ROWS * 16) + (b * PP + i0) * 16 + tid] = s;
            }
        }
    }

    grid_barrier(NB);

    // ===================== Phase 3: combine =====================
    for (int idx = blockIdx.x * 256 + tid; idx < ROWS * 16; idx += NB * 256) {
        int b = idx / (PP * 16);
        float v = __ldcg(&g_Sbias[b * 16 + (idx & 15)]);
        #pragma unroll
        for (int q = 0; q < JSEV; q++)
            v += __ldcg(&g_part[q * (ROWS * 16) + idx]);
        out[idx] = fmaxf(v, 0.f);
    }
}

// ---------------------------------------------------------------------------
extern "C" void kernel_launch(void* const* d_in, const int* in_sizes, int n_in,
                              void* d_out, int out_size)
{
    const float* feature = (const float*)d_in[0];
    const float* pe      = (const float*)d_in[1];
    const float* coords  = (const float*)d_in[2];
    const float* dW1 = (const float*)d_in[3];
    const float* db1 = (const float*)d_in[4];
    const float* dW2 = (const float*)d_in[5];
    const float* db2 = (const float*)d_in[6];
    const float* dW3 = (const float*)d_in[7];
    const float* db3 = (const float*)d_in[8];
    const float* kW1 = (const float*)d_in[9];
    const float* kb1 = (const float*)d_in[10];
    const float* kW2 = (const float*)d_in[11];
    const float* kb2 = (const float*)d_in[12];
    const float* kW3 = (const float*)d_in[13];
    const float* kb3 = (const float*)d_in[14];
    float* out = (float*)d_out;

    const int smemB = SM_TOT * (int)sizeof(float);   // 24000 B

    int dev = 0;
    cudaGetDevice(&dev);
    int sms = 0;
    cudaDeviceGetAttribute(&sms, cudaDevAttrMultiProcessorCount, dev);
    int maxB = 0;
    cudaOccupancyMaxActiveBlocksPerMultiprocessor(&maxB, fused_kernel, 256, smemB);
    if (maxB < 1) maxB = 1;
    int NB = sms * maxB;
    if (NB > NJOBS) NB = NJOBS;

    fused_kernel<<<NB, 256, smemB>>>(feature, pe, coords,
                                     dW1, db1, dW2, db2, dW3, db3,
                                     kW1, kb1, kW2, kb2, kW3, kb3,
                                     out, NB);
}